// round 6
// baseline (speedup 1.0000x reference)
#include <cuda_runtime.h>

// CRPS over a 16-member ensemble:
//   out = mean_p( (1/N) sum_i |s_i - y|  -  (1/N^2) sum_{i<j} |s_i - s_j| )
//
// R6: revert to the empirically fastest compute shape (R1 main kernel:
// 1 px/thread, TPB 256, pairwise |a-b| math with 120 independent pairs,
// plain loads, compiler-scheduled) and keep the only structural win since
// (single fused launch; last-block-finishes deterministic reduction).
// Sort-network variants (R2-R5) all lost to this shape: the serial
// comparator chain exposed more latency than the extra-but-independent
// pairwise FADDs.

#define NS 16
#define PIXELS (4 * 1 * 256 * 256)      // 262144
#define TPB 256
#define NBLOCKS (PIXELS / TPB)          // 1024

__device__ float g_partials[NBLOCKS];
__device__ unsigned int g_count = 0;

__global__ __launch_bounds__(TPB) void crps_fused_kernel(
    const float* __restrict__ samples,   // [NS, PIXELS]
    const float* __restrict__ target,    // [PIXELS]
    float* __restrict__ out)
{
    const int p = blockIdx.x * TPB + threadIdx.x;

    float v[NS];
#pragma unroll
    for (int i = 0; i < NS; i++)
        v[i] = samples[i * PIXELS + p];
    const float y = target[p];

    // term1: sum_i |v_i - y|
    float t1 = 0.f;
#pragma unroll
    for (int i = 0; i < NS; i++)
        t1 += fabsf(v[i] - y);

    // term2: sum_{i<j} |v_i - v_j|  (120 independent pairs -> high ILP)
    float t2 = 0.f;
#pragma unroll
    for (int i = 0; i < NS; i++)
#pragma unroll
        for (int j = i + 1; j < NS; j++)
            t2 += fabsf(v[i] - v[j]);

    float acc = t1 * (1.f / NS) - t2 * (1.f / (NS * NS));

    // ---- block reduction ----
#pragma unroll
    for (int off = 16; off > 0; off >>= 1)
        acc += __shfl_down_sync(0xFFFFFFFFu, acc, off);

    __shared__ float warp_sums[TPB / 32];
    const int lane = threadIdx.x & 31;
    const int wid  = threadIdx.x >> 5;
    if (lane == 0) warp_sums[wid] = acc;
    __syncthreads();

    __shared__ bool is_last;
    if (threadIdx.x == 0) {
        float bsum = 0.f;
#pragma unroll
        for (int w = 0; w < TPB / 32; w++)
            bsum += warp_sums[w];
        g_partials[blockIdx.x] = bsum;
        __threadfence();
        unsigned int done = atomicAdd(&g_count, 1u);
        is_last = (done == NBLOCKS - 1);
    }
    __syncthreads();

    // ---- last block folds all 1024 partials in a fixed order ----
    if (is_last) {
        float s = 0.f;
#pragma unroll
        for (int k = 0; k < NBLOCKS / TPB; k++)
            s += g_partials[k * TPB + threadIdx.x];
#pragma unroll
        for (int off = 16; off > 0; off >>= 1)
            s += __shfl_down_sync(0xFFFFFFFFu, s, off);
        if (lane == 0) warp_sums[wid] = s;
        __syncthreads();
        if (wid == 0) {
            float tot = (lane < TPB / 32) ? warp_sums[lane] : 0.f;
#pragma unroll
            for (int off = 4; off > 0; off >>= 1)
                tot += __shfl_down_sync(0xFFFFFFFFu, tot, off);
            if (lane == 0) {
                out[0] = tot * (1.f / PIXELS);
                g_count = 0;   // reset for next graph replay
            }
        }
    }
}

extern "C" void kernel_launch(void* const* d_in, const int* in_sizes, int n_in,
                              void* d_out, int out_size)
{
    const float* samples = (const float*)d_in[0];
    const float* target  = (const float*)d_in[1];
    float* out = (float*)d_out;

    crps_fused_kernel<<<NBLOCKS, TPB>>>(samples, target, out);
}